// round 15
// baseline (speedup 1.0000x reference)
#include <cuda_runtime.h>
#include <cuda_fp16.h>
#include <math.h>
#include <stdint.h>

#define N_TOK    4096
#define N_TOKV   8192            // both views batched
#define DIM      512
#define N_EXP    16
#define TOPK     4
#define HID      2048
#define PAIR_CAP 36864           // 32768 pairs + 16 experts * 128 pad
#define MAX_TILES 272            // 32768/128 + 16

// ---------------- device scratch -------------------------------------------
__device__ __half g_x_hi [N_TOKV * DIM];
__device__ __half g_x_lo [N_TOKV * DIM];
__device__ __half g_h_hi [N_TOKV * DIM];
__device__ __half g_h_lo [N_TOKV * DIM];
__device__ float  g_r    [N_TOKV * DIM];
__device__ __half g_pw [2 * DIM * DIM];
__device__ __half g_rw [2 * DIM * DIM];
__device__ __half g_w1 [N_EXP * DIM * HID];
__device__ __half g_w2 [N_EXP * HID * DIM];
__device__ __half g_hid [(size_t)PAIR_CAP * HID];
__device__ __half g_slot[(size_t)PAIR_CAP * DIM];
__device__ float  g_knorm[N_EXP];

__device__ int   g_pair_token[PAIR_CAP];      // zero-init: pads read row 0 (harmless)
__device__ float g_pair_gate [PAIR_CAP];
__device__ int   g_pairpos [N_TOKV * TOPK];
__device__ int   g_tok_eidx[N_TOKV * TOPK];
__device__ float g_tok_gate[N_TOKV * TOPK];
__device__ int   g_counts [N_EXP];
__device__ int   g_offsets[N_EXP + 1];
__device__ int   g_cursor [N_EXP];
__device__ int   g_tile_e [MAX_TILES];
__device__ int   g_tile_m0[MAX_TILES];
__device__ int   g_ntiles;

// ---------------- asm helpers ----------------------------------------------
__device__ __forceinline__ uint32_t smem_u32(const void* p) {
    uint32_t a;
    asm("{ .reg .u64 t; cvta.to.shared.u64 t, %1; cvt.u32.u64 %0, t; }" : "=r"(a) : "l"(p));
    return a;
}
__device__ __forceinline__ void cpa16(uint32_t s, const void* g) {
    asm volatile("cp.async.cg.shared.global [%0], [%1], 16;" :: "r"(s), "l"(g));
}
#define CP_COMMIT() asm volatile("cp.async.commit_group;" ::: "memory")
#define CP_WAIT(n)  asm volatile("cp.async.wait_group %0;" :: "n"(n) : "memory")

__device__ __forceinline__ void ldm_x4(uint32_t* r, uint32_t a) {
    asm volatile("ldmatrix.sync.aligned.m8n8.x4.shared.b16 {%0,%1,%2,%3}, [%4];"
        : "=r"(r[0]), "=r"(r[1]), "=r"(r[2]), "=r"(r[3]) : "r"(a));
}
__device__ __forceinline__ void ldm_x4_t(uint32_t* r, uint32_t a) {
    asm volatile("ldmatrix.sync.aligned.m8n8.x4.trans.shared.b16 {%0,%1,%2,%3}, [%4];"
        : "=r"(r[0]), "=r"(r[1]), "=r"(r[2]), "=r"(r[3]) : "r"(a));
}
__device__ __forceinline__ void mma_fp16(float* d, const uint32_t* a, uint32_t b0, uint32_t b1) {
    asm volatile("mma.sync.aligned.m16n8k16.row.col.f32.f16.f16.f32 "
        "{%0,%1,%2,%3}, {%4,%5,%6,%7}, {%8,%9}, {%0,%1,%2,%3};"
        : "+f"(d[0]), "+f"(d[1]), "+f"(d[2]), "+f"(d[3])
        : "r"(a[0]), "r"(a[1]), "r"(a[2]), "r"(a[3]), "r"(b0), "r"(b1));
}
__device__ __forceinline__ float gelu_exact(float x) {
    return 0.5f * x * (1.0f + erff(x * 0.70710678118654752440f));
}

// ---------------- HMMA GEMM ------------------------------------------------
// A row-major fp16 (ALIMB limbs), B row-major fp16 [K][N] (ldmatrix.trans).
// 8 warps, 64x64 warp tiles, 4-stage cp.async pipeline, ONE barrier/chunk,
// prefetch distance 2 (race-free: writes target 2-generation-old buffers).
// MODE 0: proj  (z = view from m0; +bias -> g_h hi/lo)
// MODE 1: router(z = view from m0; -> g_r fp32)
// MODE 2: ffn1  (indirect A rows; +bias,gelu -> g_hid fp16)
// MODE 3: ffn2  (+bias,*gate -> g_slot fp16)
template<int MODE, int KLEN, int NTOT, int BM, int BN, int ALIMB, int BK>
__global__ __launch_bounds__(256, 1) void mma_gemm_kernel(
    const __half* __restrict__ Ah, const __half* __restrict__ Al,
    const __half* __restrict__ B,
    const float* __restrict__ bias)
{
    constexpr int NC   = KLEN / BK;
    constexpr int KS   = BK / 16;
    constexpr int PA   = BK * 2 + 16;
    constexpr int PB   = BN * 2 + 16;
    constexpr int ABY  = BM * PA;
    constexpr int BOFF = ALIMB * ABY;
    constexpr int STG  = ALIMB * ABY + BK * PB;
    constexpr int WR   = BM / 64;
    constexpr int ARC  = BK / 8;
    constexpr int BRC  = BN / 8;
    constexpr int ACH  = BM * ARC;
    constexpr int BCH  = BK * BRC;

    int n0 = blockIdx.x * BN, m0, z;
    if (MODE <= 1) { m0 = blockIdx.y * BM; z = (m0 >= N_TOK) ? 1 : 0; }
    else {
        if ((int)blockIdx.y >= g_ntiles) return;
        z = g_tile_e[blockIdx.y]; m0 = g_tile_m0[blockIdx.y];
    }
    const __half* Bz = B + (size_t)z * KLEN * NTOT;

    extern __shared__ __align__(16) char smem[];
    uint32_t sb = smem_u32(smem);

    const int tid = threadIdx.x, lane = tid & 31, warp = tid >> 5;
    const int mw = (warp % WR) * 64, nw = (warp / WR) * 64;
    const int lr = lane & 15, lc = (lane >> 4) << 3;

    int* tok = (int*)(smem + 4 * STG);
    if (MODE == 2) {
        if (tid < BM) tok[tid] = g_pair_token[m0 + tid];
        __syncthreads();
    }

    auto load_stage = [&](int s, int c) {
        const int k0 = c * BK;
        const uint32_t base = sb + (uint32_t)s * STG;
#pragma unroll
        for (int ch = tid; ch < ACH; ch += 256) {
            int row = ch / ARC, kc = ch % ARC;
            const __half* src;
            if (MODE == 2) src = Ah + (size_t)tok[row] * KLEN + k0 + kc * 8;
            else           src = Ah + (size_t)(m0 + row) * KLEN + k0 + kc * 8;
            cpa16(base + row * PA + kc * 16, src);
            if (ALIMB == 2)
                cpa16(base + ABY + row * PA + kc * 16,
                      Al + (size_t)(m0 + row) * KLEN + k0 + kc * 8);
        }
#pragma unroll
        for (int ch = tid; ch < BCH; ch += 256) {
            int row = ch / BRC, nc = ch % BRC;
            cpa16(base + BOFF + row * PB + nc * 16,
                  Bz + (size_t)(k0 + row) * NTOT + n0 + nc * 8);
        }
    };

    float acc[4][8][4];
#pragma unroll
    for (int a = 0; a < 4; a++)
#pragma unroll
        for (int b = 0; b < 8; b++)
#pragma unroll
            for (int d = 0; d < 4; d++) acc[a][b][d] = 0.f;

    load_stage(0, 0); CP_COMMIT();
    if (NC > 1) { load_stage(1, 1); CP_COMMIT(); }

    for (int c = 0; c < NC; c++) {
        if (c + 2 < NC) { load_stage((c + 2) & 3, c + 2); CP_COMMIT(); CP_WAIT(2); }
        else if (c + 1 < NC) CP_WAIT(1);
        else CP_WAIT(0);
        __syncthreads();          // single barrier: 4 stages / distance-2 prefetch

        const uint32_t base = sb + (uint32_t)(c & 3) * STG;
#pragma unroll
        for (int ks = 0; ks < KS; ks++) {
            uint32_t a1[4][4], a2[4][4];
#pragma unroll
            for (int ms = 0; ms < 4; ms++) {
                uint32_t ad = base + (uint32_t)((mw + ms * 16 + lr) * PA + (ks * 16 + lc) * 2);
                ldm_x4(a1[ms], ad);
                if (ALIMB == 2) ldm_x4(a2[ms], ad + ABY);
            }
#pragma unroll
            for (int np = 0; np < 4; np++) {
                uint32_t bf[4];
                uint32_t bd = base + BOFF + (uint32_t)((ks * 16 + lr) * PB + (nw + np * 16 + lc) * 2);
                ldm_x4_t(bf, bd);
#pragma unroll
                for (int ms = 0; ms < 4; ms++)
#pragma unroll
                    for (int sub = 0; sub < 2; sub++) {
                        int ns = np * 2 + sub;
                        mma_fp16(acc[ms][ns], a1[ms], bf[sub*2], bf[sub*2+1]);
                        if (ALIMB == 2)
                            mma_fp16(acc[ms][ns], a2[ms], bf[sub*2], bf[sub*2+1]);
                    }
            }
        }
    }

    // ---- epilogue ----
    const int lrow = lane >> 2, lcol = (lane & 3) * 2;
#pragma unroll
    for (int ms = 0; ms < 4; ms++) {
        int r0 = m0 + mw + ms * 16 + lrow;
        float gt0 = 0.f, gt1 = 0.f;
        if (MODE == 3) { gt0 = g_pair_gate[r0]; gt1 = g_pair_gate[r0 + 8]; }
#pragma unroll
        for (int ns = 0; ns < 8; ns++) {
            int cc = n0 + nw + ns * 8 + lcol;
            float b0 = 0.f, b1 = 0.f;
            if (MODE != 1) {
                b0 = bias[(size_t)z * NTOT + cc];
                b1 = bias[(size_t)z * NTOT + cc + 1];
            }
            float v00 = acc[ms][ns][0] + b0, v01 = acc[ms][ns][1] + b1;
            float v10 = acc[ms][ns][2] + b0, v11 = acc[ms][ns][3] + b1;
            if (MODE == 2) {
                v00 = gelu_exact(v00); v01 = gelu_exact(v01);
                v10 = gelu_exact(v10); v11 = gelu_exact(v11);
            }
            if (MODE == 3) { v00 *= gt0; v01 *= gt0; v10 *= gt1; v11 *= gt1; }
            if (MODE == 1) {
                *(float2*)(g_r + (size_t)r0 * NTOT + cc)       = make_float2(v00, v01);
                *(float2*)(g_r + (size_t)(r0 + 8) * NTOT + cc) = make_float2(v10, v11);
            } else if (MODE == 2 || MODE == 3) {
                __half* OUT = (MODE == 2) ? g_hid : g_slot;
                *(__half2*)(OUT + (size_t)r0 * NTOT + cc) =
                    __halves2half2(__float2half(v00), __float2half(v01));
                *(__half2*)(OUT + (size_t)(r0 + 8) * NTOT + cc) =
                    __halves2half2(__float2half(v10), __float2half(v11));
            } else {
                __half h00 = __float2half(v00), h01 = __float2half(v01);
                __half h10 = __float2half(v10), h11 = __float2half(v11);
                *(__half2*)(g_h_hi + (size_t)r0 * NTOT + cc)       = __halves2half2(h00, h01);
                *(__half2*)(g_h_hi + (size_t)(r0 + 8) * NTOT + cc) = __halves2half2(h10, h11);
                *(__half2*)(g_h_lo + (size_t)r0 * NTOT + cc) =
                    __halves2half2(__float2half(v00 - __half2float(h00)),
                                   __float2half(v01 - __half2float(h01)));
                *(__half2*)(g_h_lo + (size_t)(r0 + 8) * NTOT + cc) =
                    __halves2half2(__float2half(v10 - __half2float(h10)),
                                   __float2half(v11 - __half2float(h11)));
            }
        }
    }
}

// ---------------- fused prep: weight converts + view splits + reset ---------
__device__ __forceinline__ void conv8_at(const float* __restrict__ in,
                                         __half* __restrict__ out, long i)
{
    float4 a = *(const float4*)(in + i);
    float4 b = *(const float4*)(in + i + 4);
    float v[8] = {a.x, a.y, a.z, a.w, b.x, b.y, b.z, b.w};
    union { __half2 p[4]; uint4 u; } ph;
#pragma unroll
    for (int j = 0; j < 4; j++)
        ph.p[j] = __halves2half2(__float2half(v[2*j]), __float2half(v[2*j+1]));
    *(uint4*)(out + i) = ph.u;
}
__device__ __forceinline__ void split8_at(const float* __restrict__ in,
                                          __half* __restrict__ hi,
                                          __half* __restrict__ lo, long i)
{
    float4 a = *(const float4*)(in + i);
    float4 b = *(const float4*)(in + i + 4);
    float v[8] = {a.x, a.y, a.z, a.w, b.x, b.y, b.z, b.w};
    union { __half2 p[4]; uint4 u; } ph, pl;
#pragma unroll
    for (int j = 0; j < 4; j++) {
        __half h0 = __float2half(v[2*j]);
        __half h1 = __float2half(v[2*j+1]);
        ph.p[j] = __halves2half2(h0, h1);
        pl.p[j] = __halves2half2(
            __float2half(v[2*j]   - __half2float(h0)),
            __float2half(v[2*j+1] - __half2float(h1)));
    }
    *(uint4*)(hi + i) = ph.u;
    *(uint4*)(lo + i) = pl.u;
}

#define C_W  ((long)N_EXP * DIM * HID / 8)
#define C_P  ((long)2 * DIM * DIM / 8)
#define C_X  ((long)N_TOK * DIM / 8)
#define PREP_CHUNKS (2*C_W + 2*C_P + 2*C_X)
#define PREP_BLOCKS ((int)((PREP_CHUNKS + 255) / 256) + 1)   // +1 tail block for knorm

__global__ __launch_bounds__(256) void prep_kernel(
    const float* __restrict__ w1, const float* __restrict__ w2,
    const float* __restrict__ pw, const float* __restrict__ rw,
    const float* __restrict__ v0, const float* __restrict__ v1,
    const float* __restrict__ keys)
{
    if (blockIdx.x == PREP_BLOCKS - 1) {
        if (threadIdx.x < N_EXP) g_counts[threadIdx.x] = 0;
        // key norms: one warp per... 16 threads, serial 512 loop each
        if (threadIdx.x < N_EXP) {
            const float* kp = keys + (size_t)threadIdx.x * DIM;
            float s = 0.f;
            for (int i = 0; i < DIM; i++) s = fmaf(kp[i], kp[i], s);
            g_knorm[threadIdx.x] = s;
        }
        return;
    }
    long id = (long)blockIdx.x * 256 + threadIdx.x;
    if (id >= PREP_CHUNKS) return;
    if (id < C_W) { conv8_at(w1, g_w1, id * 8); return; }
    id -= C_W;
    if (id < C_W) { conv8_at(w2, g_w2, id * 8); return; }
    id -= C_W;
    if (id < C_P) { conv8_at(pw, g_pw, id * 8); return; }
    id -= C_P;
    if (id < C_P) { conv8_at(rw, g_rw, id * 8); return; }
    id -= C_P;
    if (id < C_X) { split8_at(v0, g_x_hi, g_x_lo, id * 8); return; }
    id -= C_X;
    split8_at(v1, g_x_hi + (size_t)N_TOK * DIM, g_x_lo + (size_t)N_TOK * DIM, id * 8);
}

// ---------------- gate: dot-product form, float4 LDS ------------------------
// warp-per-token, 8 tokens/block. d2 = ||r||^2 - 2 r.k + ||k||^2 (fp32).
__global__ __launch_bounds__(256) void gate_kernel(const float* __restrict__ keys)
{
    __shared__ float4 ks4[N_EXP * (DIM / 4)];   // 32 KB
    __shared__ float kn[N_EXP];
    const int tid = threadIdx.x;
#pragma unroll
    for (int i = tid; i < N_EXP * (DIM / 4); i += 256)
        ks4[i] = ((const float4*)keys)[i];
    if (tid < N_EXP) kn[tid] = g_knorm[tid];
    __syncthreads();

    const int warp = tid >> 5, lane = tid & 31;
    const int t = blockIdx.x * 8 + warp;
    const float* rr = g_r + (size_t)t * DIM;
    float4 rv[4];
#pragma unroll
    for (int j = 0; j < 4; j++) rv[j] = *(const float4*)(rr + lane * 4 + 128 * j);

    float r2 = 0.f;
#pragma unroll
    for (int j = 0; j < 4; j++) {
        r2 = fmaf(rv[j].x, rv[j].x, r2); r2 = fmaf(rv[j].y, rv[j].y, r2);
        r2 = fmaf(rv[j].z, rv[j].z, r2); r2 = fmaf(rv[j].w, rv[j].w, r2);
    }
    float dot[N_EXP];
#pragma unroll
    for (int e = 0; e < N_EXP; e++) {
        float s = 0.f;
#pragma unroll
        for (int j = 0; j < 4; j++) {
            float4 k4 = ks4[e * (DIM / 4) + lane + 32 * j];
            s = fmaf(rv[j].x, k4.x, s); s = fmaf(rv[j].y, k4.y, s);
            s = fmaf(rv[j].z, k4.z, s); s = fmaf(rv[j].w, k4.w, s);
        }
        dot[e] = s;
    }
#pragma unroll
    for (int o = 16; o > 0; o >>= 1) {
        r2 += __shfl_xor_sync(0xFFFFFFFF, r2, o);
#pragma unroll
        for (int e = 0; e < N_EXP; e++)
            dot[e] += __shfl_xor_sync(0xFFFFFFFF, dot[e], o);
    }
    if (lane == 0) {
        float lg[N_EXP];
#pragma unroll
        for (int e = 0; e < N_EXP; e++)
            lg[e] = -sqrtf(fmaxf(r2 - 2.f * dot[e] + kn[e], 0.f));
        int idx[TOPK]; float val[TOPK]; bool used[N_EXP];
#pragma unroll
        for (int i = 0; i < N_EXP; i++) used[i] = false;
        for (int s2 = 0; s2 < TOPK; s2++) {
            int bi = -1; float bv = -1e30f;
            for (int i = 0; i < N_EXP; i++)
                if (!used[i] && lg[i] > bv) { bv = lg[i]; bi = i; }
            used[bi] = true; idx[s2] = bi; val[s2] = bv;
        }
        float mx = val[0], ex[TOPK], se = 0.f;
        for (int s2 = 0; s2 < TOPK; s2++) { ex[s2] = expf(val[s2] - mx); se += ex[s2]; }
        float inv = 1.0f / se;
        for (int s2 = 0; s2 < TOPK; s2++) {
            g_tok_eidx[t*TOPK + s2] = idx[s2];
            g_tok_gate[t*TOPK + s2] = ex[s2] * inv;
            atomicAdd(&g_counts[idx[s2]], 1);
        }
    }
}

__global__ void scan_kernel() {
    if (threadIdx.x == 0) {
        int o = 0, nt = 0;
        for (int e = 0; e < N_EXP; e++) {
            g_offsets[e] = o; g_cursor[e] = o;
            int seg = ((g_counts[e] + 127) >> 7) << 7;       // 128-aligned
            for (int i = 0; i < seg / 128; i++) { g_tile_e[nt] = e; g_tile_m0[nt] = o + (i << 7); nt++; }
            o += seg;
        }
        g_offsets[N_EXP] = o;
        g_ntiles = nt;
    }
}

__global__ __launch_bounds__(128) void scatter_kernel() {
    int t = blockIdx.x * 128 + threadIdx.x;
    if (t >= N_TOKV) return;
    for (int s = 0; s < TOPK; s++) {
        int e = g_tok_eidx[t*TOPK + s];
        int p = atomicAdd(&g_cursor[e], 1);
        g_pair_token[p] = t;
        g_pair_gate[p]  = g_tok_gate[t*TOPK + s];
        g_pairpos[t*TOPK + s] = p;
    }
}

// out[t] = sum over both views' 4 pairs each (8 slots, fp16 slot buffer)
__global__ __launch_bounds__(256) void combine_kernel(float* __restrict__ out)
{
    int idx = blockIdx.x * 256 + threadIdx.x;
    if (idx >= N_TOK * (DIM/4)) return;
    int t = idx >> 7, d = (idx & 127) << 2;
    float acc0 = 0.f, acc1 = 0.f, acc2 = 0.f, acc3 = 0.f;
#pragma unroll
    for (int s = 0; s < TOPK; s++) {
        int p0 = g_pairpos[t*TOPK + s];
        int p1 = g_pairpos[(t + N_TOK)*TOPK + s];
        uint2 u0 = *(const uint2*)(g_slot + (size_t)p0 * DIM + d);
        uint2 u1 = *(const uint2*)(g_slot + (size_t)p1 * DIM + d);
        float2 a0 = __half22float2(*(__half2*)&u0.x);
        float2 a1 = __half22float2(*(__half2*)&u0.y);
        float2 b0 = __half22float2(*(__half2*)&u1.x);
        float2 b1 = __half22float2(*(__half2*)&u1.y);
        acc0 += a0.x + b0.x; acc1 += a0.y + b0.y;
        acc2 += a1.x + b1.x; acc3 += a1.y + b1.y;
    }
    *(float4*)(out + (size_t)t * DIM + d) = make_float4(acc0, acc1, acc2, acc3);
}

// ---------------- host -----------------------------------------------------
#define STG_OF(BM, BN, AL, BK) ((AL) * (BM) * ((BK)*2+16) + (BK) * ((BN)*2+16))

extern "C" void kernel_launch(void* const* d_in, const int* in_sizes, int n_in,
                              void* d_out, int out_size)
{
    const float* view[2]  = {(const float*)d_in[0], (const float*)d_in[1]};
    const float* proj_w   = (const float*)d_in[2];
    const float* proj_b   = (const float*)d_in[3];
    const float* router_w = (const float*)d_in[4];
    const float* keys     = (const float*)d_in[5];
    const float* w1       = (const float*)d_in[6];
    const float* b1       = (const float*)d_in[7];
    const float* w2       = (const float*)d_in[8];
    const float* b2       = (const float*)d_in[9];
    float* out = (float*)d_out;

    void *xhi,*xlo,*hhi,*hlo,*pw,*rw,*w1p,*w2p,*hid;
    cudaGetSymbolAddress(&xhi, g_x_hi);  cudaGetSymbolAddress(&xlo, g_x_lo);
    cudaGetSymbolAddress(&hhi, g_h_hi);  cudaGetSymbolAddress(&hlo, g_h_lo);
    cudaGetSymbolAddress(&pw, g_pw);     cudaGetSymbolAddress(&rw, g_rw);
    cudaGetSymbolAddress(&w1p, g_w1);    cudaGetSymbolAddress(&w2p, g_w2);
    cudaGetSymbolAddress(&hid, g_hid);

    constexpr int SM_PR = 4 * STG_OF(128, 256, 2, 32);          // 149504
    constexpr int SM_F1 = 4 * STG_OF(128, 256, 1, 64) + 1024;   // 209920
    constexpr int SM_F2 = 4 * STG_OF(128, 256, 1, 64);          // 208896
    cudaFuncSetAttribute((const void*)mma_gemm_kernel<0,512,512,128,256,2,32>,
                         cudaFuncAttributeMaxDynamicSharedMemorySize, SM_PR);
    cudaFuncSetAttribute((const void*)mma_gemm_kernel<1,512,512,128,256,2,32>,
                         cudaFuncAttributeMaxDynamicSharedMemorySize, SM_PR);
    cudaFuncSetAttribute((const void*)mma_gemm_kernel<2,512,2048,128,256,1,64>,
                         cudaFuncAttributeMaxDynamicSharedMemorySize, SM_F1);
    cudaFuncSetAttribute((const void*)mma_gemm_kernel<3,2048,512,128,256,1,64>,
                         cudaFuncAttributeMaxDynamicSharedMemorySize, SM_F2);

    // one fused prep launch: weight converts + view splits + reset + key norms
    prep_kernel<<<PREP_BLOCKS, 256>>>(
        w1, w2, proj_w, router_w, view[0], view[1], keys);

    dim3 gpr(DIM/256, N_TOKV/128);       // (2, 64)
    dim3 gf1(HID/256, MAX_TILES);        // (8, 272)
    dim3 gf2(DIM/256, MAX_TILES);        // (2, 272)

    mma_gemm_kernel<0,512,512,128,256,2,32><<<gpr, 256, SM_PR>>>(
        (const __half*)xhi, (const __half*)xlo, (const __half*)pw, proj_b);
    mma_gemm_kernel<1,512,512,128,256,2,32><<<gpr, 256, SM_PR>>>(
        (const __half*)hhi, (const __half*)hlo, (const __half*)rw, nullptr);
    gate_kernel<<<N_TOKV/8, 256>>>(keys);
    scan_kernel<<<1, 1>>>();
    scatter_kernel<<<N_TOKV/128, 128>>>();
    mma_gemm_kernel<2,512,2048,128,256,1,64><<<gf1, 256, SM_F1>>>(
        (const __half*)hhi, nullptr, (const __half*)w1p, b1);
    mma_gemm_kernel<3,2048,512,128,256,1,64><<<gf2, 256, SM_F2>>>(
        (const __half*)hid, nullptr, (const __half*)w2p, b2);
    combine_kernel<<<(N_TOK*(DIM/4)+255)/256, 256>>>(out);
}

// round 16
// speedup vs baseline: 1.0212x; 1.0212x over previous
#include <cuda_runtime.h>
#include <cuda_fp16.h>
#include <math.h>
#include <stdint.h>

#define N_TOK    4096
#define N_TOKV   8192            // both views batched
#define DIM      512
#define N_EXP    16
#define TOPK     4
#define HID      2048
#define PAIR_CAP 36864           // 32768 pairs + 16 experts * 128 pad
#define MAX_TILES 272            // 32768/128 + 16

// ---------------- device scratch -------------------------------------------
__device__ __half g_x_hi [N_TOKV * DIM];
__device__ __half g_x_lo [N_TOKV * DIM];
__device__ __half g_h_hi [N_TOKV * DIM];
__device__ __half g_h_lo [N_TOKV * DIM];
__device__ float  g_r    [N_TOKV * DIM];
__device__ __half g_pw [2 * DIM * DIM];
__device__ __half g_rw [2 * DIM * DIM];
__device__ __half g_w1 [N_EXP * DIM * HID];
__device__ __half g_w2 [N_EXP * HID * DIM];
__device__ __half g_hid [(size_t)PAIR_CAP * HID];
__device__ __half g_slot[(size_t)PAIR_CAP * DIM];
__device__ float  g_logits[N_TOKV * N_EXP];

__device__ int   g_pair_token[PAIR_CAP];      // zero-init: pads read row 0 (harmless)
__device__ float g_pair_gate [PAIR_CAP];
__device__ int   g_pairpos [N_TOKV * TOPK];
__device__ int   g_tok_eidx[N_TOKV * TOPK];
__device__ float g_tok_gate[N_TOKV * TOPK];
__device__ int   g_counts [N_EXP];
__device__ int   g_offsets[N_EXP + 1];
__device__ int   g_cursor [N_EXP];
__device__ int   g_tile_e [MAX_TILES];
__device__ int   g_tile_m0[MAX_TILES];
__device__ int   g_ntiles;

// ---------------- asm helpers ----------------------------------------------
__device__ __forceinline__ uint32_t smem_u32(const void* p) {
    uint32_t a;
    asm("{ .reg .u64 t; cvta.to.shared.u64 t, %1; cvt.u32.u64 %0, t; }" : "=r"(a) : "l"(p));
    return a;
}
__device__ __forceinline__ void cpa16(uint32_t s, const void* g) {
    asm volatile("cp.async.cg.shared.global [%0], [%1], 16;" :: "r"(s), "l"(g));
}
#define CP_COMMIT() asm volatile("cp.async.commit_group;" ::: "memory")
#define CP_WAIT(n)  asm volatile("cp.async.wait_group %0;" :: "n"(n) : "memory")

__device__ __forceinline__ void ldm_x4(uint32_t* r, uint32_t a) {
    asm volatile("ldmatrix.sync.aligned.m8n8.x4.shared.b16 {%0,%1,%2,%3}, [%4];"
        : "=r"(r[0]), "=r"(r[1]), "=r"(r[2]), "=r"(r[3]) : "r"(a));
}
__device__ __forceinline__ void ldm_x4_t(uint32_t* r, uint32_t a) {
    asm volatile("ldmatrix.sync.aligned.m8n8.x4.trans.shared.b16 {%0,%1,%2,%3}, [%4];"
        : "=r"(r[0]), "=r"(r[1]), "=r"(r[2]), "=r"(r[3]) : "r"(a));
}
__device__ __forceinline__ void mma_fp16(float* d, const uint32_t* a, uint32_t b0, uint32_t b1) {
    asm volatile("mma.sync.aligned.m16n8k16.row.col.f32.f16.f16.f32 "
        "{%0,%1,%2,%3}, {%4,%5,%6,%7}, {%8,%9}, {%0,%1,%2,%3};"
        : "+f"(d[0]), "+f"(d[1]), "+f"(d[2]), "+f"(d[3])
        : "r"(a[0]), "r"(a[1]), "r"(a[2]), "r"(a[3]), "r"(b0), "r"(b1));
}
__device__ __forceinline__ float gelu_exact(float x) {
    return 0.5f * x * (1.0f + erff(x * 0.70710678118654752440f));
}

// ---------------- HMMA GEMM ------------------------------------------------
// A row-major fp16 (ALIMB limbs), B row-major fp16 [K][N] (ldmatrix.trans).
// 8 warps, 64x64 warp tiles, 4-stage cp.async pipeline, ONE barrier/chunk,
// prefetch distance 2 (race-free: writes target 2-generation-old buffers).
// MODE 0: proj  (z = view from m0; +bias -> g_h hi/lo)
// MODE 1: router(z = view from m0; -> g_r fp32)
// MODE 2: ffn1  (indirect A rows; +bias,gelu -> g_hid fp16)
// MODE 3: ffn2  (+bias,*gate -> g_slot fp16)
template<int MODE, int KLEN, int NTOT, int BM, int BN, int ALIMB, int BK>
__global__ __launch_bounds__(256, 1) void mma_gemm_kernel(
    const __half* __restrict__ Ah, const __half* __restrict__ Al,
    const __half* __restrict__ B,
    const float* __restrict__ bias)
{
    constexpr int NC   = KLEN / BK;
    constexpr int KS   = BK / 16;
    constexpr int PA   = BK * 2 + 16;
    constexpr int PB   = BN * 2 + 16;
    constexpr int ABY  = BM * PA;
    constexpr int BOFF = ALIMB * ABY;
    constexpr int STG  = ALIMB * ABY + BK * PB;
    constexpr int WR   = BM / 64;
    constexpr int ARC  = BK / 8;
    constexpr int BRC  = BN / 8;
    constexpr int ACH  = BM * ARC;
    constexpr int BCH  = BK * BRC;

    int n0 = blockIdx.x * BN, m0, z;
    if (MODE <= 1) { m0 = blockIdx.y * BM; z = (m0 >= N_TOK) ? 1 : 0; }
    else {
        if ((int)blockIdx.y >= g_ntiles) return;
        z = g_tile_e[blockIdx.y]; m0 = g_tile_m0[blockIdx.y];
    }
    const __half* Bz = B + (size_t)z * KLEN * NTOT;

    extern __shared__ __align__(16) char smem[];
    uint32_t sb = smem_u32(smem);

    const int tid = threadIdx.x, lane = tid & 31, warp = tid >> 5;
    const int mw = (warp % WR) * 64, nw = (warp / WR) * 64;
    const int lr = lane & 15, lc = (lane >> 4) << 3;

    int* tok = (int*)(smem + 4 * STG);
    if (MODE == 2) {
        if (tid < BM) tok[tid] = g_pair_token[m0 + tid];
        __syncthreads();
    }

    auto load_stage = [&](int s, int c) {
        const int k0 = c * BK;
        const uint32_t base = sb + (uint32_t)s * STG;
#pragma unroll
        for (int ch = tid; ch < ACH; ch += 256) {
            int row = ch / ARC, kc = ch % ARC;
            const __half* src;
            if (MODE == 2) src = Ah + (size_t)tok[row] * KLEN + k0 + kc * 8;
            else           src = Ah + (size_t)(m0 + row) * KLEN + k0 + kc * 8;
            cpa16(base + row * PA + kc * 16, src);
            if (ALIMB == 2)
                cpa16(base + ABY + row * PA + kc * 16,
                      Al + (size_t)(m0 + row) * KLEN + k0 + kc * 8);
        }
#pragma unroll
        for (int ch = tid; ch < BCH; ch += 256) {
            int row = ch / BRC, nc = ch % BRC;
            cpa16(base + BOFF + row * PB + nc * 16,
                  Bz + (size_t)(k0 + row) * NTOT + n0 + nc * 8);
        }
    };

    float acc[4][8][4];
#pragma unroll
    for (int a = 0; a < 4; a++)
#pragma unroll
        for (int b = 0; b < 8; b++)
#pragma unroll
            for (int d = 0; d < 4; d++) acc[a][b][d] = 0.f;

    load_stage(0, 0); CP_COMMIT();
    if (NC > 1) { load_stage(1, 1); CP_COMMIT(); }

    for (int c = 0; c < NC; c++) {
        if (c + 2 < NC) { load_stage((c + 2) & 3, c + 2); CP_COMMIT(); CP_WAIT(2); }
        else if (c + 1 < NC) CP_WAIT(1);
        else CP_WAIT(0);
        __syncthreads();          // single barrier: 4 stages / distance-2 prefetch

        const uint32_t base = sb + (uint32_t)(c & 3) * STG;
#pragma unroll
        for (int ks = 0; ks < KS; ks++) {
            uint32_t a1[4][4], a2[4][4];
#pragma unroll
            for (int ms = 0; ms < 4; ms++) {
                uint32_t ad = base + (uint32_t)((mw + ms * 16 + lr) * PA + (ks * 16 + lc) * 2);
                ldm_x4(a1[ms], ad);
                if (ALIMB == 2) ldm_x4(a2[ms], ad + ABY);
            }
#pragma unroll
            for (int np = 0; np < 4; np++) {
                uint32_t bf[4];
                uint32_t bd = base + BOFF + (uint32_t)((ks * 16 + lr) * PB + (nw + np * 16 + lc) * 2);
                ldm_x4_t(bf, bd);
#pragma unroll
                for (int ms = 0; ms < 4; ms++)
#pragma unroll
                    for (int sub = 0; sub < 2; sub++) {
                        int ns = np * 2 + sub;
                        mma_fp16(acc[ms][ns], a1[ms], bf[sub*2], bf[sub*2+1]);
                        if (ALIMB == 2)
                            mma_fp16(acc[ms][ns], a2[ms], bf[sub*2], bf[sub*2+1]);
                    }
            }
        }
    }

    // ---- epilogue ----
    const int lrow = lane >> 2, lcol = (lane & 3) * 2;
#pragma unroll
    for (int ms = 0; ms < 4; ms++) {
        int r0 = m0 + mw + ms * 16 + lrow;
        float gt0 = 0.f, gt1 = 0.f;
        if (MODE == 3) { gt0 = g_pair_gate[r0]; gt1 = g_pair_gate[r0 + 8]; }
#pragma unroll
        for (int ns = 0; ns < 8; ns++) {
            int cc = n0 + nw + ns * 8 + lcol;
            float b0 = 0.f, b1 = 0.f;
            if (MODE != 1) {
                b0 = bias[(size_t)z * NTOT + cc];
                b1 = bias[(size_t)z * NTOT + cc + 1];
            }
            float v00 = acc[ms][ns][0] + b0, v01 = acc[ms][ns][1] + b1;
            float v10 = acc[ms][ns][2] + b0, v11 = acc[ms][ns][3] + b1;
            if (MODE == 2) {
                v00 = gelu_exact(v00); v01 = gelu_exact(v01);
                v10 = gelu_exact(v10); v11 = gelu_exact(v11);
            }
            if (MODE == 3) { v00 *= gt0; v01 *= gt0; v10 *= gt1; v11 *= gt1; }
            if (MODE == 1) {
                *(float2*)(g_r + (size_t)r0 * NTOT + cc)       = make_float2(v00, v01);
                *(float2*)(g_r + (size_t)(r0 + 8) * NTOT + cc) = make_float2(v10, v11);
            } else if (MODE == 2 || MODE == 3) {
                __half* OUT = (MODE == 2) ? g_hid : g_slot;
                *(__half2*)(OUT + (size_t)r0 * NTOT + cc) =
                    __halves2half2(__float2half(v00), __float2half(v01));
                *(__half2*)(OUT + (size_t)(r0 + 8) * NTOT + cc) =
                    __halves2half2(__float2half(v10), __float2half(v11));
            } else {
                __half h00 = __float2half(v00), h01 = __float2half(v01);
                __half h10 = __float2half(v10), h11 = __float2half(v11);
                *(__half2*)(g_h_hi + (size_t)r0 * NTOT + cc)       = __halves2half2(h00, h01);
                *(__half2*)(g_h_hi + (size_t)(r0 + 8) * NTOT + cc) = __halves2half2(h10, h11);
                *(__half2*)(g_h_lo + (size_t)r0 * NTOT + cc) =
                    __halves2half2(__float2half(v00 - __half2float(h00)),
                                   __float2half(v01 - __half2float(h01)));
                *(__half2*)(g_h_lo + (size_t)(r0 + 8) * NTOT + cc) =
                    __halves2half2(__float2half(v10 - __half2float(h10)),
                                   __float2half(v11 - __half2float(h11)));
            }
        }
    }
}

// ---------------- fused prep: weight converts + view splits + reset ---------
__device__ __forceinline__ void conv8_at(const float* __restrict__ in,
                                         __half* __restrict__ out, long i)
{
    float4 a = *(const float4*)(in + i);
    float4 b = *(const float4*)(in + i + 4);
    float v[8] = {a.x, a.y, a.z, a.w, b.x, b.y, b.z, b.w};
    union { __half2 p[4]; uint4 u; } ph;
#pragma unroll
    for (int j = 0; j < 4; j++)
        ph.p[j] = __halves2half2(__float2half(v[2*j]), __float2half(v[2*j+1]));
    *(uint4*)(out + i) = ph.u;
}
__device__ __forceinline__ void split8_at(const float* __restrict__ in,
                                          __half* __restrict__ hi,
                                          __half* __restrict__ lo, long i)
{
    float4 a = *(const float4*)(in + i);
    float4 b = *(const float4*)(in + i + 4);
    float v[8] = {a.x, a.y, a.z, a.w, b.x, b.y, b.z, b.w};
    union { __half2 p[4]; uint4 u; } ph, pl;
#pragma unroll
    for (int j = 0; j < 4; j++) {
        __half h0 = __float2half(v[2*j]);
        __half h1 = __float2half(v[2*j+1]);
        ph.p[j] = __halves2half2(h0, h1);
        pl.p[j] = __halves2half2(
            __float2half(v[2*j]   - __half2float(h0)),
            __float2half(v[2*j+1] - __half2float(h1)));
    }
    *(uint4*)(hi + i) = ph.u;
    *(uint4*)(lo + i) = pl.u;
}

#define C_W  ((long)N_EXP * DIM * HID / 8)
#define C_P  ((long)2 * DIM * DIM / 8)
#define C_X  ((long)N_TOK * DIM / 8)
#define PREP_CHUNKS (2*C_W + 2*C_P + 2*C_X)

__global__ __launch_bounds__(256) void prep_kernel(
    const float* __restrict__ w1, const float* __restrict__ w2,
    const float* __restrict__ pw, const float* __restrict__ rw,
    const float* __restrict__ v0, const float* __restrict__ v1)
{
    long id = (long)blockIdx.x * 256 + threadIdx.x;
    if (blockIdx.x == 0 && threadIdx.x < N_EXP) g_counts[threadIdx.x] = 0;
    if (id >= PREP_CHUNKS) return;
    if (id < C_W) { conv8_at(w1, g_w1, id * 8); return; }
    id -= C_W;
    if (id < C_W) { conv8_at(w2, g_w2, id * 8); return; }
    id -= C_W;
    if (id < C_P) { conv8_at(pw, g_pw, id * 8); return; }
    id -= C_P;
    if (id < C_P) { conv8_at(rw, g_rw, id * 8); return; }
    id -= C_P;
    if (id < C_X) { split8_at(v0, g_x_hi, g_x_lo, id * 8); return; }
    id -= C_X;
    split8_at(v1, g_x_hi + (size_t)N_TOK * DIM, g_x_lo + (size_t)N_TOK * DIM, id * 8);
}

// ---------------- gate: logits only (identical math to R14) -----------------
__global__ __launch_bounds__(256) void gate_kernel(const float* __restrict__ keys)
{
    __shared__ float ks[N_EXP][DIM];
    const int tid = threadIdx.x;
    for (int i = tid; i < N_EXP * DIM; i += 256)
        ks[i >> 9][i & 511] = keys[i];
    __syncthreads();

    const int warp = tid >> 5, lane = tid & 31;
    const int t = blockIdx.x * 8 + warp;
    const float* rr = g_r + (size_t)t * DIM;
    float rv[16];
#pragma unroll
    for (int j = 0; j < 16; j++) rv[j] = rr[lane + 32 * j];

    float lg[N_EXP];
#pragma unroll
    for (int e = 0; e < N_EXP; e++) {
        float s = 0.f;
#pragma unroll
        for (int j = 0; j < 16; j++) {
            float d = rv[j] - ks[e][lane + 32 * j];
            s = fmaf(d, d, s);
        }
#pragma unroll
        for (int o = 16; o > 0; o >>= 1)
            s += __shfl_xor_sync(0xFFFFFFFF, s, o);
        lg[e] = -sqrtf(fmaxf(s, 0.f));
    }
    if (lane == 0) {
        float* Lp = g_logits + (size_t)t * N_EXP;
        *(float4*)(Lp + 0)  = make_float4(lg[0],  lg[1],  lg[2],  lg[3]);
        *(float4*)(Lp + 4)  = make_float4(lg[4],  lg[5],  lg[6],  lg[7]);
        *(float4*)(Lp + 8)  = make_float4(lg[8],  lg[9],  lg[10], lg[11]);
        *(float4*)(Lp + 12) = make_float4(lg[12], lg[13], lg[14], lg[15]);
    }
}

// top-4 + softmax + counts, one thread per token (identical compare order)
__global__ __launch_bounds__(256) void topk_kernel()
{
    int t = blockIdx.x * 256 + threadIdx.x;
    if (t >= N_TOKV) return;
    const float* Lp = g_logits + (size_t)t * N_EXP;
    float4 l0 = *(const float4*)(Lp + 0);
    float4 l1 = *(const float4*)(Lp + 4);
    float4 l2 = *(const float4*)(Lp + 8);
    float4 l3 = *(const float4*)(Lp + 12);
    float lg[N_EXP] = {l0.x,l0.y,l0.z,l0.w, l1.x,l1.y,l1.z,l1.w,
                       l2.x,l2.y,l2.z,l2.w, l3.x,l3.y,l3.z,l3.w};
    int idx[TOPK]; float val[TOPK]; bool used[N_EXP];
#pragma unroll
    for (int i = 0; i < N_EXP; i++) used[i] = false;
    for (int s2 = 0; s2 < TOPK; s2++) {
        int bi = -1; float bv = -1e30f;
        for (int i = 0; i < N_EXP; i++)
            if (!used[i] && lg[i] > bv) { bv = lg[i]; bi = i; }
        used[bi] = true; idx[s2] = bi; val[s2] = bv;
    }
    float mx = val[0], ex[TOPK], se = 0.f;
    for (int s2 = 0; s2 < TOPK; s2++) { ex[s2] = expf(val[s2] - mx); se += ex[s2]; }
    float inv = 1.0f / se;
    for (int s2 = 0; s2 < TOPK; s2++) {
        g_tok_eidx[t*TOPK + s2] = idx[s2];
        g_tok_gate[t*TOPK + s2] = ex[s2] * inv;
        atomicAdd(&g_counts[idx[s2]], 1);
    }
}

__global__ void scan_kernel() {
    if (threadIdx.x == 0) {
        int o = 0, nt = 0;
        for (int e = 0; e < N_EXP; e++) {
            g_offsets[e] = o; g_cursor[e] = o;
            int seg = ((g_counts[e] + 127) >> 7) << 7;       // 128-aligned
            for (int i = 0; i < seg / 128; i++) { g_tile_e[nt] = e; g_tile_m0[nt] = o + (i << 7); nt++; }
            o += seg;
        }
        g_offsets[N_EXP] = o;
        g_ntiles = nt;
    }
}

__global__ __launch_bounds__(128) void scatter_kernel() {
    int t = blockIdx.x * 128 + threadIdx.x;
    if (t >= N_TOKV) return;
    for (int s = 0; s < TOPK; s++) {
        int e = g_tok_eidx[t*TOPK + s];
        int p = atomicAdd(&g_cursor[e], 1);
        g_pair_token[p] = t;
        g_pair_gate[p]  = g_tok_gate[t*TOPK + s];
        g_pairpos[t*TOPK + s] = p;
    }
}

// out[t] = sum over both views' 4 pairs each (8 slots, fp16 slot buffer)
__global__ __launch_bounds__(256) void combine_kernel(float* __restrict__ out)
{
    int idx = blockIdx.x * 256 + threadIdx.x;
    if (idx >= N_TOK * (DIM/4)) return;
    int t = idx >> 7, d = (idx & 127) << 2;
    float acc0 = 0.f, acc1 = 0.f, acc2 = 0.f, acc3 = 0.f;
#pragma unroll
    for (int s = 0; s < TOPK; s++) {
        int p0 = g_pairpos[t*TOPK + s];
        int p1 = g_pairpos[(t + N_TOK)*TOPK + s];
        uint2 u0 = *(const uint2*)(g_slot + (size_t)p0 * DIM + d);
        uint2 u1 = *(const uint2*)(g_slot + (size_t)p1 * DIM + d);
        float2 a0 = __half22float2(*(__half2*)&u0.x);
        float2 a1 = __half22float2(*(__half2*)&u0.y);
        float2 b0 = __half22float2(*(__half2*)&u1.x);
        float2 b1 = __half22float2(*(__half2*)&u1.y);
        acc0 += a0.x + b0.x; acc1 += a0.y + b0.y;
        acc2 += a1.x + b1.x; acc3 += a1.y + b1.y;
    }
    *(float4*)(out + (size_t)t * DIM + d) = make_float4(acc0, acc1, acc2, acc3);
}

// ---------------- host -----------------------------------------------------
#define STG_OF(BM, BN, AL, BK) ((AL) * (BM) * ((BK)*2+16) + (BK) * ((BN)*2+16))

extern "C" void kernel_launch(void* const* d_in, const int* in_sizes, int n_in,
                              void* d_out, int out_size)
{
    const float* view[2]  = {(const float*)d_in[0], (const float*)d_in[1]};
    const float* proj_w   = (const float*)d_in[2];
    const float* proj_b   = (const float*)d_in[3];
    const float* router_w = (const float*)d_in[4];
    const float* keys     = (const float*)d_in[5];
    const float* w1       = (const float*)d_in[6];
    const float* b1       = (const float*)d_in[7];
    const float* w2       = (const float*)d_in[8];
    const float* b2       = (const float*)d_in[9];
    float* out = (float*)d_out;

    void *xhi,*xlo,*hhi,*hlo,*pw,*rw,*w1p,*w2p,*hid;
    cudaGetSymbolAddress(&xhi, g_x_hi);  cudaGetSymbolAddress(&xlo, g_x_lo);
    cudaGetSymbolAddress(&hhi, g_h_hi);  cudaGetSymbolAddress(&hlo, g_h_lo);
    cudaGetSymbolAddress(&pw, g_pw);     cudaGetSymbolAddress(&rw, g_rw);
    cudaGetSymbolAddress(&w1p, g_w1);    cudaGetSymbolAddress(&w2p, g_w2);
    cudaGetSymbolAddress(&hid, g_hid);

    constexpr int SM_PR = 4 * STG_OF(128, 256, 2, 32);          // 149504
    constexpr int SM_F1 = 4 * STG_OF(128, 256, 1, 64) + 1024;   // 209920
    constexpr int SM_F2 = 4 * STG_OF(128, 256, 1, 64);          // 208896
    cudaFuncSetAttribute((const void*)mma_gemm_kernel<0,512,512,128,256,2,32>,
                         cudaFuncAttributeMaxDynamicSharedMemorySize, SM_PR);
    cudaFuncSetAttribute((const void*)mma_gemm_kernel<1,512,512,128,256,2,32>,
                         cudaFuncAttributeMaxDynamicSharedMemorySize, SM_PR);
    cudaFuncSetAttribute((const void*)mma_gemm_kernel<2,512,2048,128,256,1,64>,
                         cudaFuncAttributeMaxDynamicSharedMemorySize, SM_F1);
    cudaFuncSetAttribute((const void*)mma_gemm_kernel<3,2048,512,128,256,1,64>,
                         cudaFuncAttributeMaxDynamicSharedMemorySize, SM_F2);

    // one fused prep launch: all weight converts + both view splits + reset
    prep_kernel<<<(int)((PREP_CHUNKS + 255) / 256), 256>>>(
        w1, w2, proj_w, router_w, view[0], view[1]);

    dim3 gpr(DIM/256, N_TOKV/128);       // (2, 64)
    dim3 gf1(HID/256, MAX_TILES);        // (8, 272)
    dim3 gf2(DIM/256, MAX_TILES);        // (2, 272)

    mma_gemm_kernel<0,512,512,128,256,2,32><<<gpr, 256, SM_PR>>>(
        (const __half*)xhi, (const __half*)xlo, (const __half*)pw, proj_b);
    mma_gemm_kernel<1,512,512,128,256,2,32><<<gpr, 256, SM_PR>>>(
        (const __half*)hhi, (const __half*)hlo, (const __half*)rw, nullptr);
    gate_kernel<<<N_TOKV/8, 256>>>(keys);
    topk_kernel<<<N_TOKV/256, 256>>>();
    scan_kernel<<<1, 1>>>();
    scatter_kernel<<<N_TOKV/128, 128>>>();
    mma_gemm_kernel<2,512,2048,128,256,1,64><<<gf1, 256, SM_F1>>>(
        (const __half*)hhi, nullptr, (const __half*)w1p, b1);
    mma_gemm_kernel<3,2048,512,128,256,1,64><<<gf2, 256, SM_F2>>>(
        (const __half*)hid, nullptr, (const __half*)w2p, b2);
    combine_kernel<<<(N_TOK*(DIM/4)+255)/256, 256>>>(out);
}